// round 6
// baseline (speedup 1.0000x reference)
#include <cuda_runtime.h>
#include <cuda_bf16.h>

// Problem constants
#define NB 4
#define NC 64
#define NH 128
#define NW 128
#define NN 16
#define NPIX (NB*NH*NW)   // 65536 pixels

typedef unsigned long long u64;

// Scratch (allocation-free rule: __device__ globals)
static __device__ float g_delta[(size_t)NPIX*64];   // [p][c]
static __device__ float g_u[(size_t)NPIX*64];       // [p][c]
static __device__ float g_Bc[(size_t)NPIX*16];      // [p][n]
static __device__ float g_Cc[(size_t)NPIX*16];      // [p][n]
static __device__ float g_yh[(size_t)NPIX*64];      // [p][c]
static __device__ float g_yv[(size_t)NPIX*64];      // [p][c]

__device__ __forceinline__ float fexp2(float x) {
    float r;
    asm("ex2.approx.f32 %0, %1;" : "=f"(r) : "f"(x));
    return r;
}
__device__ __forceinline__ u64 pack2(float lo, float hi) {
    u64 r; asm("mov.b64 %0, {%1, %2};" : "=l"(r) : "f"(lo), "f"(hi)); return r;
}
__device__ __forceinline__ void unpack2(u64 v, float& lo, float& hi) {
    asm("mov.b64 {%0, %1}, %2;" : "=f"(lo), "=f"(hi) : "l"(v));
}
__device__ __forceinline__ u64 fma2(u64 a, u64 b, u64 c) {
    u64 d; asm("fma.rn.f32x2 %0, %1, %2, %3;" : "=l"(d) : "l"(a), "l"(b), "l"(c)); return d;
}
__device__ __forceinline__ u64 mul2(u64 a, u64 b) {
    u64 d; asm("mul.rn.f32x2 %0, %1, %2;" : "=l"(d) : "l"(a), "l"(b)); return d;
}

// ---------------------------------------------------------------------------
// Projection (setup folded in): one block per (b,h) row of 128 pixels;
// 256 threads = 2 groups of 128; group g computes output chunks 3g..3g+2.
// Weights (dt-fold + B/C rows) rebuilt per block from xw/dtw — trivial cost.
// u kept ONLY in packed f32x2 form (64 regs) to avoid spills.
// ---------------------------------------------------------------------------
__global__ __launch_bounds__(256) void proj_kernel(const float* __restrict__ x,
                                                   const float* __restrict__ xw,   // [36,64]
                                                   const float* __restrict__ dtw,  // [64,4]
                                                   const float* __restrict__ dtb)  // [64]
{
    __shared__ __align__(16) float s_w[96*64];      // 24 KB
    __shared__ float s_tile[2][128*17];             // per-group staging
    __shared__ float s_bias[64];

    int bh  = blockIdx.x;          // 0..511
    int b   = bh >> 7;
    int h   = bh & 127;
    int w   = threadIdx.x & 127;   // pixel
    int grp = threadIdx.x >> 7;    // output group

    // Build folded weights: rows 0..63 = dtw@xw[0:4], rows 64..95 = xw[4:36]
    for (int i = threadIdx.x; i < 96*64; i += 256) {
        int r = i >> 6, c = i & 63;
        float v;
        if (r < 64) {
            v = dtw[r*4+0]*xw[0*64+c] + dtw[r*4+1]*xw[1*64+c]
              + dtw[r*4+2]*xw[2*64+c] + dtw[r*4+3]*xw[3*64+c];
        } else {
            v = xw[(r - 60)*64 + c];
        }
        s_w[i] = v;
    }
    if (threadIdx.x < 64) s_bias[threadIdx.x] = dtb[threadIdx.x];

    // Load channel vector x[b, :, h, w] directly into packed pairs
    u64 u2[32];
    const float* xp = x + ((size_t)(b*64)*128 + h)*128 + w;
    #pragma unroll
    for (int c2 = 0; c2 < 32; c2++) {
        float lo = xp[(size_t)(2*c2)  *16384];
        float hi = xp[(size_t)(2*c2+1)*16384];
        u2[c2] = pack2(lo, hi);
    }

    __syncthreads();

    size_t pbase = (size_t)bh * 128;

    for (int ch = 0; ch < 3; ch++) {
        int chunk = grp*3 + ch;        // grp0: 0,1,2  grp1: 3,4,5
        int o0 = chunk * 16;
        #pragma unroll 4
        for (int j = 0; j < 16; j++) {
            const ulonglong2* wr = (const ulonglong2*)(s_w + (o0 + j)*64);
            u64 acc2 = 0ull;
            #pragma unroll
            for (int c = 0; c < 16; c++) {
                ulonglong2 wv = wr[c];            // 4 floats = 2 packed pairs
                acc2 = fma2(u2[2*c],   wv.x, acc2);
                acc2 = fma2(u2[2*c+1], wv.y, acc2);
            }
            float lo, hi; unpack2(acc2, lo, hi);
            s_tile[grp][w*17 + j] = lo + hi;
        }
        __syncthreads();
        #pragma unroll
        for (int it = 0; it < 16; it++) {
            int idx = it*128 + w;
            int pix = idx >> 4;
            int j   = idx & 15;
            float v = s_tile[grp][pix*17 + j];
            if (chunk < 4) {
                int o = chunk*16 + j;
                v += s_bias[o];
                v = (v > 15.f) ? v : __logf(1.f + __expf(v));   // softplus
                g_delta[(pbase + pix)*64 + o] = v;
            } else if (chunk == 4) {
                g_Bc[(pbase + pix)*16 + j] = v;
            } else {
                g_Cc[(pbase + pix)*16 + j] = v;
            }
        }
        __syncthreads();
    }

    // u transpose to [p][c]: group g writes channel blocks 2g, 2g+1
    #pragma unroll
    for (int k = 0; k < 2; k++) {
        int cc = grp*2 + k;
        #pragma unroll
        for (int jj = 0; jj < 8; jj++) {
            float a, bb; unpack2(u2[cc*8 + jj], a, bb);
            s_tile[grp][w*17 + 2*jj]   = a;
            s_tile[grp][w*17 + 2*jj+1] = bb;
        }
        __syncthreads();
        #pragma unroll
        for (int it = 0; it < 16; it++) {
            int idx = it*128 + w;
            int pix = idx >> 4;
            int j   = idx & 15;
            g_u[(pbase + pix)*64 + cc*16 + j] = s_tile[grp][pix*17 + j];
        }
        __syncthreads();
    }
}

// ---------------------------------------------------------------------------
// Scan: thread = (sequence, channel, half-of-states); packed f32x2 state
// updates, software-pipelined loads, shfl reduction. A2 built per-thread.
// Blocks 0..511 horizontal, 512..1023 vertical.
// ---------------------------------------------------------------------------
__global__ __launch_bounds__(128) void scan_kernel(const float* __restrict__ A_log)
{
    int tid  = threadIdx.x;
    int d    = tid >> 1;          // channel 0..63
    int half = tid & 1;           // state group (0: n=0..7, 1: n=8..15)
    int blk  = blockIdx.x;        // 0..1023
    int dir  = blk >> 9;          // 0 = H, 1 = V
    int s    = blk & 511;
    int b    = s >> 7;
    int rc   = s & 127;

    size_t pix0;
    int stride;
    float* __restrict__ yout;
    if (dir == 0) { pix0 = ((size_t)(b*128 + rc))*128; stride = 1;   yout = g_yh; }
    else          { pix0 = (size_t)b*16384 + rc;       stride = 128; yout = g_yv; }

    // A2 = -exp(A_log) * log2(e) for this thread's 8 states
    u64 A22[4];
    #pragma unroll
    for (int q = 0; q < 4; q++) {
        const float* ap = A_log + d*16 + half*8 + 2*q;
        float a0 = -__expf(ap[0]) * 1.4426950408889634f;
        float a1 = -__expf(ap[1]) * 1.4426950408889634f;
        A22[q] = pack2(a0, a1);
    }

    u64 hs2[4];
    #pragma unroll
    for (int q = 0; q < 4; q++) hs2[q] = 0ull;

    size_t p = pix0;

    // Prologue loads: this half's 8 states = 32B of B and of C
    float delta = g_delta[p*64 + d];
    float uu    = g_u[p*64 + d];
    ulonglong2 Bv = *(const ulonglong2*)(g_Bc + p*16 + half*8);
    ulonglong2 Cv = *(const ulonglong2*)(g_Cc + p*16 + half*8);
    ulonglong2 Bw = *(const ulonglong2*)(g_Bc + p*16 + half*8 + 4);
    ulonglong2 Cw = *(const ulonglong2*)(g_Cc + p*16 + half*8 + 4);

    for (int l = 0; l < 128; l++) {
        size_t pn = p + (l < 127 ? stride : 0);
        float delta_n = g_delta[pn*64 + d];
        float uu_n    = g_u[pn*64 + d];
        ulonglong2 Bn = *(const ulonglong2*)(g_Bc + pn*16 + half*8);
        ulonglong2 Cn = *(const ulonglong2*)(g_Cc + pn*16 + half*8);
        ulonglong2 Bm = *(const ulonglong2*)(g_Bc + pn*16 + half*8 + 4);
        ulonglong2 Cm = *(const ulonglong2*)(g_Cc + pn*16 + half*8 + 4);

        float du = delta * uu;
        u64 du2 = pack2(du, du);
        u64 delta2 = pack2(delta, delta);
        u64 y2 = 0ull;

#define SSM_STEP2(q, bv, cv)                                       \
        {                                                          \
            u64 e2 = mul2(delta2, A22[q]);                         \
            float e0, e1; unpack2(e2, e0, e1);                     \
            u64 dA2 = pack2(fexp2(e0), fexp2(e1));                 \
            hs2[q] = fma2(dA2, hs2[q], mul2(du2, (bv)));           \
            y2 = fma2(hs2[q], (cv), y2);                           \
        }
        SSM_STEP2(0, Bv.x, Cv.x);
        SSM_STEP2(1, Bv.y, Cv.y);
        SSM_STEP2(2, Bw.x, Cw.x);
        SSM_STEP2(3, Bw.y, Cw.y);
#undef SSM_STEP2

        float ylo, yhi; unpack2(y2, ylo, yhi);
        float y = ylo + yhi;
        y += __shfl_xor_sync(0xffffffffu, y, 1);
        if (half == 0) yout[p*64 + d] = y;

        delta = delta_n; uu = uu_n;
        Bv = Bn; Bw = Bm; Cv = Cn; Cw = Cm;
        p = pn;
    }
}

// ---------------------------------------------------------------------------
// Combine + transpose: out[b,c,h,w] = yh[p][c] + yv[p][c] + 2*D[c]*x[b,c,h,w]
// float4 loads of yh/yv; conflict-free smem staging.
// ---------------------------------------------------------------------------
__global__ __launch_bounds__(256) void combine_kernel(const float* __restrict__ x,
                                                      const float* __restrict__ Dv,
                                                      float* __restrict__ out)
{
    __shared__ float s[32][33];
    int t    = blockIdx.x;
    int tile = t & 7;          // 2 c-tiles x 4 w-tiles
    int bh   = t >> 3;
    int b    = bh >> 7;
    int h    = bh & 127;
    int c0   = (tile & 1) * 32;
    int w0   = (tile >> 1) * 32;
    size_t pbase = (size_t)bh * 128;

    // Phase 1: load 32w x 32c tile of yh+yv with float4 (thread = (row, c-group))
    {
        int row = threadIdx.x >> 3;       // 0..31 (w within tile)
        int cg  = threadIdx.x & 7;        // 0..7  (group of 4 channels)
        size_t idx = (pbase + w0 + row)*64 + c0 + cg*4;
        float4 a = *(const float4*)(g_yh + idx);
        float4 v = *(const float4*)(g_yv + idx);
        s[row][cg*4+0] = a.x + v.x;
        s[row][cg*4+1] = a.y + v.y;
        s[row][cg*4+2] = a.z + v.z;
        s[row][cg*4+3] = a.w + v.w;
    }
    __syncthreads();

    // Phase 2: write transposed, fused with D*x skip term
    int tx = threadIdx.x & 31;
    int ty = threadIdx.x >> 5;            // 0..7
    #pragma unroll
    for (int i = 0; i < 4; i++) {
        int ci = ty + i*8;
        int c  = c0 + ci;
        size_t xi = (((size_t)(b*64 + c))*128 + h)*128 + w0 + tx;
        out[xi] = s[tx][ci] + 2.f * Dv[c] * x[xi];
    }
}

// ---------------------------------------------------------------------------
extern "C" void kernel_launch(void* const* d_in, const int* in_sizes, int n_in,
                              void* d_out, int out_size)
{
    const float* x     = (const float*)d_in[0];   // [4,64,128,128]
    const float* A_log = (const float*)d_in[1];   // [64,16]
    const float* Dv    = (const float*)d_in[2];   // [64]
    const float* xw    = (const float*)d_in[3];   // [36,64]
    const float* dtw   = (const float*)d_in[4];   // [64,4]
    const float* dtb   = (const float*)d_in[5];   // [64]
    float* out = (float*)d_out;

    proj_kernel<<<NB*NH, 256>>>(x, xw, dtw, dtb);
    scan_kernel<<<1024, 128>>>(A_log);
    combine_kernel<<<NB*NH*8, 256>>>(x, Dv, out);
}

// round 7
// speedup vs baseline: 1.1182x; 1.1182x over previous
#include <cuda_runtime.h>
#include <cuda_bf16.h>

// Problem constants
#define NB 4
#define NC 64
#define NH 128
#define NW 128
#define NN 16
#define NPIX (NB*NH*NW)   // 65536 pixels

typedef unsigned long long u64;

// Scratch (allocation-free rule: __device__ globals)
static __device__ float g_delta[(size_t)NPIX*64];   // [p][c]
static __device__ float g_u[(size_t)NPIX*64];       // [p][c]
static __device__ float g_Bc[(size_t)NPIX*16];      // [p][n]
static __device__ float g_Cc[(size_t)NPIX*16];      // [p][n]
static __device__ float g_yh[(size_t)NPIX*64];      // [p][c]
static __device__ float g_yv[(size_t)NPIX*64];      // [p][c]

__device__ __forceinline__ float fexp2(float x) {
    float r;
    asm("ex2.approx.f32 %0, %1;" : "=f"(r) : "f"(x));
    return r;
}
__device__ __forceinline__ u64 pack2(float lo, float hi) {
    u64 r; asm("mov.b64 %0, {%1, %2};" : "=l"(r) : "f"(lo), "f"(hi)); return r;
}
__device__ __forceinline__ void unpack2(u64 v, float& lo, float& hi) {
    asm("mov.b64 {%0, %1}, %2;" : "=f"(lo), "=f"(hi) : "l"(v));
}
__device__ __forceinline__ u64 fma2(u64 a, u64 b, u64 c) {
    u64 d; asm("fma.rn.f32x2 %0, %1, %2, %3;" : "=l"(d) : "l"(a), "l"(b), "l"(c)); return d;
}
__device__ __forceinline__ u64 mul2(u64 a, u64 b) {
    u64 d; asm("mul.rn.f32x2 %0, %1, %2;" : "=l"(d) : "l"(a), "l"(b)); return d;
}

// ---------------------------------------------------------------------------
// Projection as smem-tiled GEMM. Block = one (b,h) row: [96 outs] x [128 pix],
// K = 64 channels, split into two 32-channel halves through a smem x-tile.
// Thread (ty 0..15, tx 0..15) owns outs {ty+16i} x pixel-pairs {2tx+32jp}:
// 24 packed f32x2 accumulators, 24 independent FMA chains.
// ---------------------------------------------------------------------------
#define WT_STRIDE 100   // s_wt row pad ([k][o])
#define X_STRIDE  134   // s_x  row pad ([k][pix]), even => float2-aligned

__global__ __launch_bounds__(256, 3) void proj_kernel(const float* __restrict__ x,
                                                      const float* __restrict__ xw,   // [36,64]
                                                      const float* __restrict__ dtw,  // [64,4]
                                                      const float* __restrict__ dtb)  // [64]
{
    __shared__ __align__(16) float s_wt[64*WT_STRIDE];  // [k][o]; reused as staging
    __shared__ __align__(16) float s_x[32*X_STRIDE];    // [k][pix]
    __shared__ float s_bias[64];

    int bh  = blockIdx.x;          // 0..511
    int b   = bh >> 7;
    int h   = bh & 127;
    int tid = threadIdx.x;
    int tx  = tid & 15;            // pixel-pair group
    int ty  = tid >> 4;            // output base (0..15)

    // Fold weights: out rows 0..63 = dtw@xw[0:4]  (delta pre-act),
    //               rows 64..95 = xw[4:36] (B then C). Stored [k][o].
    for (int i = tid; i < 96*64; i += 256) {
        int r = i >> 6, c = i & 63;
        float v;
        if (r < 64) {
            v = dtw[r*4+0]*xw[0*64+c] + dtw[r*4+1]*xw[1*64+c]
              + dtw[r*4+2]*xw[2*64+c] + dtw[r*4+3]*xw[3*64+c];
        } else {
            v = xw[(r - 60)*64 + c];
        }
        s_wt[c*WT_STRIDE + r] = v;
    }
    if (tid < 64) s_bias[tid] = dtb[tid];

    size_t pbase = (size_t)bh * 128;

    u64 acc2[6][4];
    #pragma unroll
    for (int i = 0; i < 6; i++)
        #pragma unroll
        for (int jp = 0; jp < 4; jp++) acc2[i][jp] = 0ull;

    for (int half = 0; half < 2; half++) {
        __syncthreads();   // (half 0: also covers weight-fold completion)
        // Load x tile: 32 channels x 128 pixels, coalesced rows
        #pragma unroll
        for (int it = 0; it < 16; it++) {
            int idx = it*256 + tid;
            int cl  = idx >> 7;      // 0..31
            int w   = idx & 127;
            s_x[cl*X_STRIDE + w] =
                x[(((size_t)(b*64 + half*32 + cl))*128 + h)*128 + w];
        }
        __syncthreads();

        // Write u transposed to [p][c] straight from the smem tile (coalesced:
        // each warp writes one pixel's 32 contiguous channels = 128B)
        #pragma unroll
        for (int it = 0; it < 16; it++) {
            int idx = it*256 + tid;
            int pix = idx >> 5;
            int c   = idx & 31;
            g_u[(pbase + pix)*64 + half*32 + c] = s_x[c*X_STRIDE + pix];
        }

        // GEMM mainloop over this half's 32 channels
        #pragma unroll 4
        for (int k = 0; k < 32; k++) {
            const float* wrow = s_wt + (half*32 + k)*WT_STRIDE + ty;
            u64 w2[6];
            #pragma unroll
            for (int i = 0; i < 6; i++) {
                float wv = wrow[16*i];
                w2[i] = pack2(wv, wv);
            }
            u64 xp[4];
            #pragma unroll
            for (int jp = 0; jp < 4; jp++) {
                float2 xv = *(const float2*)(s_x + k*X_STRIDE + 2*tx + 32*jp);
                xp[jp] = pack2(xv.x, xv.y);
            }
            #pragma unroll
            for (int i = 0; i < 6; i++)
                #pragma unroll
                for (int jp = 0; jp < 4; jp++)
                    acc2[i][jp] = fma2(w2[i], xp[jp], acc2[i][jp]);
        }
    }

    __syncthreads();

    // Epilogue: per 16-output chunk i, stage [pix][j] in smem (reusing s_wt),
    // then drain coalesced with activation applied for the delta chunks.
    float* s_st = s_wt;
    for (int i = 0; i < 6; i++) {
        #pragma unroll
        for (int jp = 0; jp < 4; jp++) {
            float lo, hi; unpack2(acc2[i][jp], lo, hi);
            int pp = 2*tx + 32*jp;
            s_st[pp*17 + ty]       = lo;
            s_st[(pp + 1)*17 + ty] = hi;
        }
        __syncthreads();
        #pragma unroll
        for (int it = 0; it < 8; it++) {
            int idx = it*256 + tid;
            int pix = idx >> 4;
            int j   = idx & 15;
            float v = s_st[pix*17 + j];
            if (i < 4) {
                int o = i*16 + j;
                v += s_bias[o];
                v = (v > 15.f) ? v : __logf(1.f + __expf(v));   // softplus
                g_delta[(pbase + pix)*64 + o] = v;
            } else if (i == 4) {
                g_Bc[(pbase + pix)*16 + j] = v;
            } else {
                g_Cc[(pbase + pix)*16 + j] = v;
            }
        }
        __syncthreads();
    }
}

// ---------------------------------------------------------------------------
// Scan: thread = (sequence, channel, half-of-states); packed f32x2 state
// updates, software-pipelined loads, shfl reduction. (unchanged from R5)
// ---------------------------------------------------------------------------
__global__ __launch_bounds__(128) void scan_kernel(const float* __restrict__ A_log)
{
    int tid  = threadIdx.x;
    int d    = tid >> 1;          // channel 0..63
    int half = tid & 1;           // state group (0: n=0..7, 1: n=8..15)
    int blk  = blockIdx.x;        // 0..1023
    int dir  = blk >> 9;          // 0 = H, 1 = V
    int s    = blk & 511;
    int b    = s >> 7;
    int rc   = s & 127;

    size_t pix0;
    int stride;
    float* __restrict__ yout;
    if (dir == 0) { pix0 = ((size_t)(b*128 + rc))*128; stride = 1;   yout = g_yh; }
    else          { pix0 = (size_t)b*16384 + rc;       stride = 128; yout = g_yv; }

    u64 A22[4];
    #pragma unroll
    for (int q = 0; q < 4; q++) {
        const float* ap = A_log + d*16 + half*8 + 2*q;
        float a0 = -__expf(ap[0]) * 1.4426950408889634f;
        float a1 = -__expf(ap[1]) * 1.4426950408889634f;
        A22[q] = pack2(a0, a1);
    }

    u64 hs2[4];
    #pragma unroll
    for (int q = 0; q < 4; q++) hs2[q] = 0ull;

    size_t p = pix0;

    float delta = g_delta[p*64 + d];
    float uu    = g_u[p*64 + d];
    ulonglong2 Bv = *(const ulonglong2*)(g_Bc + p*16 + half*8);
    ulonglong2 Cv = *(const ulonglong2*)(g_Cc + p*16 + half*8);
    ulonglong2 Bw = *(const ulonglong2*)(g_Bc + p*16 + half*8 + 4);
    ulonglong2 Cw = *(const ulonglong2*)(g_Cc + p*16 + half*8 + 4);

    for (int l = 0; l < 128; l++) {
        size_t pn = p + (l < 127 ? stride : 0);
        float delta_n = g_delta[pn*64 + d];
        float uu_n    = g_u[pn*64 + d];
        ulonglong2 Bn = *(const ulonglong2*)(g_Bc + pn*16 + half*8);
        ulonglong2 Cn = *(const ulonglong2*)(g_Cc + pn*16 + half*8);
        ulonglong2 Bm = *(const ulonglong2*)(g_Bc + pn*16 + half*8 + 4);
        ulonglong2 Cm = *(const ulonglong2*)(g_Cc + pn*16 + half*8 + 4);

        float du = delta * uu;
        u64 du2 = pack2(du, du);
        u64 delta2 = pack2(delta, delta);
        u64 y2 = 0ull;

#define SSM_STEP2(q, bv, cv)                                       \
        {                                                          \
            u64 e2 = mul2(delta2, A22[q]);                         \
            float e0, e1; unpack2(e2, e0, e1);                     \
            u64 dA2 = pack2(fexp2(e0), fexp2(e1));                 \
            hs2[q] = fma2(dA2, hs2[q], mul2(du2, (bv)));           \
            y2 = fma2(hs2[q], (cv), y2);                           \
        }
        SSM_STEP2(0, Bv.x, Cv.x);
        SSM_STEP2(1, Bv.y, Cv.y);
        SSM_STEP2(2, Bw.x, Cw.x);
        SSM_STEP2(3, Bw.y, Cw.y);
#undef SSM_STEP2

        float ylo, yhi; unpack2(y2, ylo, yhi);
        float y = ylo + yhi;
        y += __shfl_xor_sync(0xffffffffu, y, 1);
        if (half == 0) yout[p*64 + d] = y;

        delta = delta_n; uu = uu_n;
        Bv = Bn; Bw = Bm; Cv = Cn; Cw = Cm;
        p = pn;
    }
}

// ---------------------------------------------------------------------------
// Combine + transpose (unchanged from R5)
// ---------------------------------------------------------------------------
__global__ __launch_bounds__(256) void combine_kernel(const float* __restrict__ x,
                                                      const float* __restrict__ Dv,
                                                      float* __restrict__ out)
{
    __shared__ float s[32][33];
    int t    = blockIdx.x;
    int tile = t & 7;
    int bh   = t >> 3;
    int b    = bh >> 7;
    int h    = bh & 127;
    int c0   = (tile & 1) * 32;
    int w0   = (tile >> 1) * 32;
    size_t pbase = (size_t)bh * 128;

    {
        int row = threadIdx.x >> 3;
        int cg  = threadIdx.x & 7;
        size_t idx = (pbase + w0 + row)*64 + c0 + cg*4;
        float4 a = *(const float4*)(g_yh + idx);
        float4 v = *(const float4*)(g_yv + idx);
        s[row][cg*4+0] = a.x + v.x;
        s[row][cg*4+1] = a.y + v.y;
        s[row][cg*4+2] = a.z + v.z;
        s[row][cg*4+3] = a.w + v.w;
    }
    __syncthreads();

    int tx = threadIdx.x & 31;
    int ty = threadIdx.x >> 5;
    #pragma unroll
    for (int i = 0; i < 4; i++) {
        int ci = ty + i*8;
        int c  = c0 + ci;
        size_t xi = (((size_t)(b*64 + c))*128 + h)*128 + w0 + tx;
        out[xi] = s[tx][ci] + 2.f * Dv[c] * x[xi];
    }
}

// ---------------------------------------------------------------------------
extern "C" void kernel_launch(void* const* d_in, const int* in_sizes, int n_in,
                              void* d_out, int out_size)
{
    const float* x     = (const float*)d_in[0];   // [4,64,128,128]
    const float* A_log = (const float*)d_in[1];   // [64,16]
    const float* Dv    = (const float*)d_in[2];   // [64]
    const float* xw    = (const float*)d_in[3];   // [36,64]
    const float* dtw   = (const float*)d_in[4];   // [64,4]
    const float* dtb   = (const float*)d_in[5];   // [64]
    float* out = (float*)d_out;

    proj_kernel<<<NB*NH, 256>>>(x, xw, dtw, dtb);
    scan_kernel<<<1024, 128>>>(A_log);
    combine_kernel<<<NB*NH*8, 256>>>(x, Dv, out);
}